// round 1
// baseline (speedup 1.0000x reference)
#include <cuda_runtime.h>
#include <math.h>

// Problem constants
constexpr int cB  = 4;
constexpr int cS  = 2048;
constexpr int cD  = 1024;
constexpr int cH  = 16;
constexpr int cDK = 64;
constexpr int cBH = cB * cH;   // 64

// Scratch (static __device__ globals: allowed; no runtime allocation)
__device__ float g_q[(size_t)cBH * cS * cDK];          // 33.5 MB  (B,H,S,DK)
__device__ float g_k[(size_t)cBH * cS * cDK];          // 33.5 MB
__device__ float g_v[(size_t)cBH * cS * cDK];          // 33.5 MB
__device__ float g_p[(size_t)cBH * cS * cS];           // 1 GiB    (B,H,S,S) scores -> probs (in place)
__device__ float g_ctx[(size_t)cB * cS * cD];          // 33.5 MB  (B,S,H,DK) context

// ---------------------------------------------------------------------------
// Kernel 1: input projections.  C[m,n] = sum_k X[m,k] * W[n,k]   (NT GEMM)
// X: (8192,1024) row-major, W: (1024,1024) row-major.  Output scattered into
// head-major layout out[((b*H+h)*S+s)*DK+dk],  m=b*S+s, n=h*DK+dk.
// blockIdx.z in {0,1,2} selects (query,W0)->g_q, (key,W1)->g_k, (value,W2)->g_v.
// Tiles: 64x64x16, 256 threads, 4x4 per thread.
// ---------------------------------------------------------------------------
__global__ void proj_kernel(const float* __restrict__ q_in,
                            const float* __restrict__ k_in,
                            const float* __restrict__ v_in,
                            const float* __restrict__ w_in)
{
    const int z = blockIdx.z;
    const float* X = (z == 0) ? q_in : (z == 1) ? k_in : v_in;
    const float* W = w_in + (size_t)z * cD * cD;
    float* out     = (z == 0) ? g_q : (z == 1) ? g_k : g_v;

    __shared__ float As[16][64];
    __shared__ float Bs[16][64];

    const int tid = threadIdx.x;
    const int tx  = tid & 15;
    const int ty  = tid >> 4;
    const int rowBase = blockIdx.y * 64;
    const int colBase = blockIdx.x * 64;

    float acc[4][4] = {};

    for (int k0 = 0; k0 < cD; k0 += 16) {
#pragma unroll
        for (int t = 0; t < 4; t++) {
            int e = tid + t * 256;          // 0..1023
            int r = e >> 4;                 // 0..63
            int c = e & 15;                 // 0..15
            As[c][r] = X[(size_t)(rowBase + r) * cD + k0 + c];
            Bs[c][r] = W[(size_t)(colBase + r) * cD + k0 + c];
        }
        __syncthreads();
#pragma unroll
        for (int kk = 0; kk < 16; kk++) {
            float a[4], b[4];
#pragma unroll
            for (int i = 0; i < 4; i++) a[i] = As[kk][ty * 4 + i];
#pragma unroll
            for (int j = 0; j < 4; j++) b[j] = Bs[kk][tx * 4 + j];
#pragma unroll
            for (int i = 0; i < 4; i++)
#pragma unroll
                for (int j = 0; j < 4; j++)
                    acc[i][j] += a[i] * b[j];
        }
        __syncthreads();
    }

#pragma unroll
    for (int i = 0; i < 4; i++) {
        int m  = rowBase + ty * 4 + i;
        int bb = m / cS;
        int ss = m % cS;
#pragma unroll
        for (int j = 0; j < 4; j++) {
            int n  = colBase + tx * 4 + j;
            int hh = n / cDK;
            int dd = n % cDK;
            out[((size_t)(bb * cH + hh) * cS + ss) * cDK + dd] = acc[i][j];
        }
    }
}

// ---------------------------------------------------------------------------
// Kernel 2: scores.  Per (b,h): P[q,k] = 0.125 * dot(Q[q,:], K[k,:])
// NT GEMM  M=N=2048, Kdim=64.  grid (32,32,64).
// ---------------------------------------------------------------------------
__global__ void scores_kernel()
{
    const int bh = blockIdx.z;
    const float* Q = g_q + (size_t)bh * cS * cDK;
    const float* K = g_k + (size_t)bh * cS * cDK;
    float* P       = g_p + (size_t)bh * cS * cS;

    __shared__ float As[16][64];
    __shared__ float Bs[16][64];

    const int tid = threadIdx.x;
    const int tx  = tid & 15;
    const int ty  = tid >> 4;
    const int rowBase = blockIdx.y * 64;
    const int colBase = blockIdx.x * 64;

    float acc[4][4] = {};

    for (int k0 = 0; k0 < cDK; k0 += 16) {
#pragma unroll
        for (int t = 0; t < 4; t++) {
            int e = tid + t * 256;
            int r = e >> 4;
            int c = e & 15;
            As[c][r] = Q[(size_t)(rowBase + r) * cDK + k0 + c];
            Bs[c][r] = K[(size_t)(colBase + r) * cDK + k0 + c];
        }
        __syncthreads();
#pragma unroll
        for (int kk = 0; kk < 16; kk++) {
            float a[4], b[4];
#pragma unroll
            for (int i = 0; i < 4; i++) a[i] = As[kk][ty * 4 + i];
#pragma unroll
            for (int j = 0; j < 4; j++) b[j] = Bs[kk][tx * 4 + j];
#pragma unroll
            for (int i = 0; i < 4; i++)
#pragma unroll
                for (int j = 0; j < 4; j++)
                    acc[i][j] += a[i] * b[j];
        }
        __syncthreads();
    }

    const float scale = 0.125f;   // 1/sqrt(64)
#pragma unroll
    for (int i = 0; i < 4; i++) {
        int m = rowBase + ty * 4 + i;
#pragma unroll
        for (int j = 0; j < 4; j++) {
            int n = colBase + tx * 4 + j;
            P[(size_t)m * cS + n] = acc[i][j] * scale;
        }
    }
}

// ---------------------------------------------------------------------------
// Kernel 3: row softmax in place.  One block (256 thr) per row of 2048.
// grid (S, B*H).
// ---------------------------------------------------------------------------
__global__ void softmax_kernel()
{
    float* p = g_p + ((size_t)blockIdx.y * cS + blockIdx.x) * cS;
    const int tid = threadIdx.x;

    float v[8];
    float m = -1e30f;
#pragma unroll
    for (int i = 0; i < 8; i++) {
        v[i] = p[tid + i * 256];
        m = fmaxf(m, v[i]);
    }

    __shared__ float red[256];
    red[tid] = m;
    __syncthreads();
    for (int s = 128; s > 0; s >>= 1) {
        if (tid < s) red[tid] = fmaxf(red[tid], red[tid + s]);
        __syncthreads();
    }
    m = red[0];
    __syncthreads();

    float l = 0.0f;
#pragma unroll
    for (int i = 0; i < 8; i++) {
        v[i] = __expf(v[i] - m);
        l += v[i];
    }
    red[tid] = l;
    __syncthreads();
    for (int s = 128; s > 0; s >>= 1) {
        if (tid < s) red[tid] += red[tid + s];
        __syncthreads();
    }
    const float inv = 1.0f / red[0];

#pragma unroll
    for (int i = 0; i < 8; i++)
        p[tid + i * 256] = v[i] * inv;
}

// ---------------------------------------------------------------------------
// Kernel 4: similarity mean over heads.  out2[b,q,k] = (1/H) sum_h P[b,h,q,k]
// grid (S, B), 256 threads.
// ---------------------------------------------------------------------------
__global__ void simmean_kernel(float* __restrict__ out2)
{
    const int q = blockIdx.x;
    const int b = blockIdx.y;
    const int tid = threadIdx.x;

    for (int k = tid; k < cS; k += 256) {
        float acc = 0.0f;
#pragma unroll
        for (int h = 0; h < cH; h++)
            acc += g_p[((size_t)(b * cH + h) * cS + q) * cS + k];
        out2[((size_t)b * cS + q) * cS + k] = acc * (1.0f / cH);
    }
}

// ---------------------------------------------------------------------------
// Kernel 5: PV.  Per (b,h): ctx[q,d] = sum_k P[q,k] * V[k,d]
// NN GEMM  M=2048, N=64, Kdim=2048.  grid (1,32,64).
// Writes context in (B,S,H,DK) layout for the output projection.
// ---------------------------------------------------------------------------
__global__ void pv_kernel()
{
    const int bh = blockIdx.z;
    const int b  = bh / cH;
    const int h  = bh % cH;
    const float* P = g_p + (size_t)bh * cS * cS;
    const float* V = g_v + (size_t)bh * cS * cDK;

    __shared__ float As[16][64];
    __shared__ float Bs[16][64];

    const int tid = threadIdx.x;
    const int tx  = tid & 15;
    const int ty  = tid >> 4;
    const int rowBase = blockIdx.y * 64;
    // colBase = 0 (N = 64 = one tile)

    float acc[4][4] = {};

    for (int k0 = 0; k0 < cS; k0 += 16) {
#pragma unroll
        for (int t = 0; t < 4; t++) {
            int e = tid + t * 256;
            // A tile: 64 rows x 16 k
            int ar = e >> 4;
            int ac = e & 15;
            As[ac][ar] = P[(size_t)(rowBase + ar) * cS + k0 + ac];
            // B tile: 16 k x 64 cols
            int br = e >> 6;      // 0..15
            int bc = e & 63;      // 0..63
            Bs[br][bc] = V[(size_t)(k0 + br) * cDK + bc];
        }
        __syncthreads();
#pragma unroll
        for (int kk = 0; kk < 16; kk++) {
            float a[4], b2[4];
#pragma unroll
            for (int i = 0; i < 4; i++) a[i] = As[kk][ty * 4 + i];
#pragma unroll
            for (int j = 0; j < 4; j++) b2[j] = Bs[kk][tx * 4 + j];
#pragma unroll
            for (int i = 0; i < 4; i++)
#pragma unroll
                for (int j = 0; j < 4; j++)
                    acc[i][j] += a[i] * b2[j];
        }
        __syncthreads();
    }

#pragma unroll
    for (int i = 0; i < 4; i++) {
        int q = rowBase + ty * 4 + i;
#pragma unroll
        for (int j = 0; j < 4; j++) {
            int d = tx * 4 + j;
            g_ctx[((size_t)(b * cS + q) * cH + h) * cDK + d] = acc[i][j];
        }
    }
}

// ---------------------------------------------------------------------------
// Kernel 6: output projection.  C[m,n] = sum_k ctx[m,k] * Wout[n,k]
// NT GEMM  M=8192, N=1024, Kdim=1024.  C -> d_out (row-major B*S x D).
// ---------------------------------------------------------------------------
__global__ void outproj_kernel(const float* __restrict__ w_out,
                               float* __restrict__ out)
{
    __shared__ float As[16][64];
    __shared__ float Bs[16][64];

    const int tid = threadIdx.x;
    const int tx  = tid & 15;
    const int ty  = tid >> 4;
    const int rowBase = blockIdx.y * 64;
    const int colBase = blockIdx.x * 64;

    float acc[4][4] = {};

    for (int k0 = 0; k0 < cD; k0 += 16) {
#pragma unroll
        for (int t = 0; t < 4; t++) {
            int e = tid + t * 256;
            int r = e >> 4;
            int c = e & 15;
            As[c][r] = g_ctx[(size_t)(rowBase + r) * cD + k0 + c];
            Bs[c][r] = w_out[(size_t)(colBase + r) * cD + k0 + c];
        }
        __syncthreads();
#pragma unroll
        for (int kk = 0; kk < 16; kk++) {
            float a[4], b[4];
#pragma unroll
            for (int i = 0; i < 4; i++) a[i] = As[kk][ty * 4 + i];
#pragma unroll
            for (int j = 0; j < 4; j++) b[j] = Bs[kk][tx * 4 + j];
#pragma unroll
            for (int i = 0; i < 4; i++)
#pragma unroll
                for (int j = 0; j < 4; j++)
                    acc[i][j] += a[i] * b[j];
        }
        __syncthreads();
    }

#pragma unroll
    for (int i = 0; i < 4; i++) {
        int m = rowBase + ty * 4 + i;
#pragma unroll
        for (int j = 0; j < 4; j++) {
            int n = colBase + tx * 4 + j;
            out[(size_t)m * cD + n] = acc[i][j];
        }
    }
}

// ---------------------------------------------------------------------------
// Launch.  Inputs: 0=query 1=key 2=value 3=input_weight(3,D,D) 4=output_weight.
// Output: [attn (B,S,D) | sim_mean (B,S,S)] fp32, concatenated.
// ---------------------------------------------------------------------------
extern "C" void kernel_launch(void* const* d_in, const int* in_sizes, int n_in,
                              void* d_out, int out_size)
{
    const float* q_in  = (const float*)d_in[0];
    const float* k_in  = (const float*)d_in[1];
    const float* v_in  = (const float*)d_in[2];
    const float* w_in  = (const float*)d_in[3];
    const float* w_out = (const float*)d_in[4];

    float* out  = (float*)d_out;                       // attn: B*S*D floats
    float* sim  = out + (size_t)cB * cS * cD;          // sim_mean: B*S*S floats

    // 1. Projections (Q,K,V)
    proj_kernel<<<dim3(cD / 64, (cB * cS) / 64, 3), 256>>>(q_in, k_in, v_in, w_in);

    // 2. Scores = scale * Q K^T  per (b,h)
    scores_kernel<<<dim3(cS / 64, cS / 64, cBH), 256>>>();

    // 3. Softmax rows in place
    softmax_kernel<<<dim3(cS, cBH), 256>>>();

    // 4. Mean over heads -> second output
    simmean_kernel<<<dim3(cS, cB), 256>>>(sim);

    // 5. Context = P V  per (b,h), written (B,S,H,DK)
    pv_kernel<<<dim3(1, cS / 64, cBH), 256>>>();

    // 6. Output projection -> first output
    outproj_kernel<<<dim3(cD / 64, (cB * cS) / 64), 256>>>(w_out, out);
}

// round 3
// speedup vs baseline: 2.0196x; 2.0196x over previous
#include <cuda_runtime.h>
#include <math.h>

// Problem constants
constexpr int cB  = 4;
constexpr int cS  = 2048;
constexpr int cD  = 1024;
constexpr int cH  = 16;
constexpr int cDK = 64;
constexpr int cBH = cB * cH;   // 64

// Scratch (static __device__ globals)
__device__ float g_q[(size_t)cBH * cS * cDK];          // (B,H,S,DK), pre-scaled by 0.125
__device__ float g_k[(size_t)cBH * cS * cDK];
__device__ float g_v[(size_t)cBH * cS * cDK];
__device__ float g_p[(size_t)cBH * cS * cS];           // 1 GiB scores -> probs (in place)
__device__ float g_ctx[(size_t)cB * cS * cD];          // (B,S,H,DK)

// ---------------------------------------------------------------------------
// Kernel 1: input projections.  C[m,n] = sum_k X[m,k] * W[n,k]   (NT)
// 128x128x16 tile, 256 threads, 8x8 per thread.  Q output scaled by 0.125.
// ---------------------------------------------------------------------------
__global__ __launch_bounds__(256)
void proj_kernel(const float* __restrict__ q_in,
                 const float* __restrict__ k_in,
                 const float* __restrict__ v_in,
                 const float* __restrict__ w_in)
{
    const int z = blockIdx.z;
    const float* X = (z == 0) ? q_in : (z == 1) ? k_in : v_in;
    const float* W = w_in + (size_t)z * cD * cD;
    float* out     = (z == 0) ? g_q : (z == 1) ? g_k : g_v;

    __shared__ float As[16 * 132];
    __shared__ float Bs[16 * 132];

    const int tid = threadIdx.x;
    const int tx  = tid & 15;
    const int ty  = tid >> 4;
    const int rowBase = blockIdx.y * 128;
    const int colBase = blockIdx.x * 128;

    float acc[8][8] = {};

    for (int k0 = 0; k0 < cD; k0 += 16) {
#pragma unroll
        for (int t = 0; t < 2; t++) {
            int idx = tid + t * 256;
            int r   = idx >> 2;
            int c4  = (idx & 3) * 4;
            float4 a = *(const float4*)&X[(size_t)(rowBase + r) * cD + k0 + c4];
            As[(c4 + 0) * 132 + r] = a.x;
            As[(c4 + 1) * 132 + r] = a.y;
            As[(c4 + 2) * 132 + r] = a.z;
            As[(c4 + 3) * 132 + r] = a.w;
            float4 b = *(const float4*)&W[(size_t)(colBase + r) * cD + k0 + c4];
            Bs[(c4 + 0) * 132 + r] = b.x;
            Bs[(c4 + 1) * 132 + r] = b.y;
            Bs[(c4 + 2) * 132 + r] = b.z;
            Bs[(c4 + 3) * 132 + r] = b.w;
        }
        __syncthreads();
#pragma unroll
        for (int kk = 0; kk < 16; kk++) {
            float a[8], b[8];
            *(float4*)&a[0] = *(float4*)&As[kk * 132 + ty * 8];
            *(float4*)&a[4] = *(float4*)&As[kk * 132 + ty * 8 + 4];
            *(float4*)&b[0] = *(float4*)&Bs[kk * 132 + tx * 8];
            *(float4*)&b[4] = *(float4*)&Bs[kk * 132 + tx * 8 + 4];
#pragma unroll
            for (int i = 0; i < 8; i++)
#pragma unroll
                for (int j = 0; j < 8; j++)
                    acc[i][j] += a[i] * b[j];
        }
        __syncthreads();
    }

    const float scale = (z == 0) ? 0.125f : 1.0f;   // fold 1/sqrt(dk) into Q
    const int nBase = colBase + tx * 8;
    const int hh = nBase >> 6;
    const int dd = nBase & 63;
#pragma unroll
    for (int i = 0; i < 8; i++) {
        int m  = rowBase + ty * 8 + i;
        int bb = m >> 11;        // / cS
        int ss = m & 2047;       // % cS
        float* dst = &out[((size_t)(bb * cH + hh) * cS + ss) * cDK + dd];
        float4 v0 = make_float4(acc[i][0] * scale, acc[i][1] * scale,
                                acc[i][2] * scale, acc[i][3] * scale);
        float4 v1 = make_float4(acc[i][4] * scale, acc[i][5] * scale,
                                acc[i][6] * scale, acc[i][7] * scale);
        *(float4*)&dst[0] = v0;
        *(float4*)&dst[4] = v1;
    }
}

// ---------------------------------------------------------------------------
// Kernel 2: scores.  Per (b,h): P[q,k] = dot(Qs[q,:], K[k,:])  (Q pre-scaled)
// 128x128x16 tile.  grid (16,16,64).
// ---------------------------------------------------------------------------
__global__ __launch_bounds__(256)
void scores_kernel()
{
    const int bh = blockIdx.z;
    const float* Q = g_q + (size_t)bh * cS * cDK;
    const float* K = g_k + (size_t)bh * cS * cDK;
    float* P       = g_p + (size_t)bh * cS * cS;

    __shared__ float As[16 * 132];
    __shared__ float Bs[16 * 132];

    const int tid = threadIdx.x;
    const int tx  = tid & 15;
    const int ty  = tid >> 4;
    const int rowBase = blockIdx.y * 128;
    const int colBase = blockIdx.x * 128;

    float acc[8][8] = {};

    for (int k0 = 0; k0 < cDK; k0 += 16) {
#pragma unroll
        for (int t = 0; t < 2; t++) {
            int idx = tid + t * 256;
            int r   = idx >> 2;
            int c4  = (idx & 3) * 4;
            float4 a = *(const float4*)&Q[(size_t)(rowBase + r) * cDK + k0 + c4];
            As[(c4 + 0) * 132 + r] = a.x;
            As[(c4 + 1) * 132 + r] = a.y;
            As[(c4 + 2) * 132 + r] = a.z;
            As[(c4 + 3) * 132 + r] = a.w;
            float4 b = *(const float4*)&K[(size_t)(colBase + r) * cDK + k0 + c4];
            Bs[(c4 + 0) * 132 + r] = b.x;
            Bs[(c4 + 1) * 132 + r] = b.y;
            Bs[(c4 + 2) * 132 + r] = b.z;
            Bs[(c4 + 3) * 132 + r] = b.w;
        }
        __syncthreads();
#pragma unroll
        for (int kk = 0; kk < 16; kk++) {
            float a[8], b[8];
            *(float4*)&a[0] = *(float4*)&As[kk * 132 + ty * 8];
            *(float4*)&a[4] = *(float4*)&As[kk * 132 + ty * 8 + 4];
            *(float4*)&b[0] = *(float4*)&Bs[kk * 132 + tx * 8];
            *(float4*)&b[4] = *(float4*)&Bs[kk * 132 + tx * 8 + 4];
#pragma unroll
            for (int i = 0; i < 8; i++)
#pragma unroll
                for (int j = 0; j < 8; j++)
                    acc[i][j] += a[i] * b[j];
        }
        __syncthreads();
    }

#pragma unroll
    for (int i = 0; i < 8; i++) {
        int m = rowBase + ty * 8 + i;
        float* dst = &P[(size_t)m * cS + colBase + tx * 8];
        *(float4*)&dst[0] = *(float4*)&acc[i][0];
        *(float4*)&dst[4] = *(float4*)&acc[i][4];
    }
}

// ---------------------------------------------------------------------------
// Kernel 3: fused softmax (in place) + head-mean.  One block per (b,q),
// loops over the 16 heads, accumulating mean in registers.  grid (S, B).
// ---------------------------------------------------------------------------
__global__ __launch_bounds__(256)
void softmax_simmean_kernel(float* __restrict__ sim)
{
    const int q = blockIdx.x;
    const int b = blockIdx.y;
    const int tid  = threadIdx.x;
    const int lane = tid & 31;
    const int wid  = tid >> 5;

    __shared__ float wred[8];
    float acc[8] = {};

    for (int h = 0; h < cH; h++) {
        float* p = g_p + ((size_t)(b * cH + h) * cS + q) * cS;

        float v[8];
        *(float4*)&v[0] = *(float4*)&p[tid * 8];
        *(float4*)&v[4] = *(float4*)&p[tid * 8 + 4];

        float m = v[0];
#pragma unroll
        for (int i = 1; i < 8; i++) m = fmaxf(m, v[i]);
#pragma unroll
        for (int o = 16; o > 0; o >>= 1) m = fmaxf(m, __shfl_xor_sync(0xffffffffu, m, o));
        if (lane == 0) wred[wid] = m;
        __syncthreads();
        float bm = wred[0];
#pragma unroll
        for (int w = 1; w < 8; w++) bm = fmaxf(bm, wred[w]);
        __syncthreads();

        float l = 0.0f;
#pragma unroll
        for (int i = 0; i < 8; i++) { v[i] = __expf(v[i] - bm); l += v[i]; }
#pragma unroll
        for (int o = 16; o > 0; o >>= 1) l += __shfl_xor_sync(0xffffffffu, l, o);
        if (lane == 0) wred[wid] = l;
        __syncthreads();
        float bl = wred[0];
#pragma unroll
        for (int w = 1; w < 8; w++) bl += wred[w];
        __syncthreads();

        const float inv = 1.0f / bl;
#pragma unroll
        for (int i = 0; i < 8; i++) { v[i] *= inv; acc[i] += v[i]; }
        *(float4*)&p[tid * 8]     = *(float4*)&v[0];
        *(float4*)&p[tid * 8 + 4] = *(float4*)&v[4];
    }

    float* s = sim + ((size_t)b * cS + q) * cS;
    float o0[8];
#pragma unroll
    for (int i = 0; i < 8; i++) o0[i] = acc[i] * (1.0f / cH);
    *(float4*)&s[tid * 8]     = *(float4*)&o0[0];
    *(float4*)&s[tid * 8 + 4] = *(float4*)&o0[4];
}

// ---------------------------------------------------------------------------
// Kernel 4: PV.  Per (b,h): ctx[q,d] = sum_k P[q,k] * V[k,d]   (NN)
// 128x64x16 tile, 256 threads, 8x4 per thread.  grid (16, 64).
// Output written (B,S,H,DK).
// ---------------------------------------------------------------------------
__global__ __launch_bounds__(256)
void pv_kernel()
{
    const int bh = blockIdx.y;
    const int b  = bh / cH;
    const int h  = bh % cH;
    const float* P = g_p + (size_t)bh * cS * cS;
    const float* V = g_v + (size_t)bh * cS * cDK;

    __shared__ float As[16 * 132];
    __shared__ float Bs[16 * 64];

    const int tid = threadIdx.x;
    const int tx  = tid & 15;
    const int ty  = tid >> 4;
    const int rowBase = blockIdx.x * 128;

    float acc[8][4] = {};

    for (int k0 = 0; k0 < cS; k0 += 16) {
#pragma unroll
        for (int t = 0; t < 2; t++) {
            int idx = tid + t * 256;
            int r   = idx >> 2;
            int c4  = (idx & 3) * 4;
            float4 a = *(const float4*)&P[(size_t)(rowBase + r) * cS + k0 + c4];
            As[(c4 + 0) * 132 + r] = a.x;
            As[(c4 + 1) * 132 + r] = a.y;
            As[(c4 + 2) * 132 + r] = a.z;
            As[(c4 + 3) * 132 + r] = a.w;
        }
        {
            int r  = tid >> 4;          // 0..15
            int c4 = (tid & 15) * 4;    // 0..60
            *(float4*)&Bs[r * 64 + c4] = *(const float4*)&V[(size_t)(k0 + r) * cDK + c4];
        }
        __syncthreads();
#pragma unroll
        for (int kk = 0; kk < 16; kk++) {
            float a[8], bv[4];
            *(float4*)&a[0]  = *(float4*)&As[kk * 132 + ty * 8];
            *(float4*)&a[4]  = *(float4*)&As[kk * 132 + ty * 8 + 4];
            *(float4*)&bv[0] = *(float4*)&Bs[kk * 64 + tx * 4];
#pragma unroll
            for (int i = 0; i < 8; i++)
#pragma unroll
                for (int j = 0; j < 4; j++)
                    acc[i][j] += a[i] * bv[j];
        }
        __syncthreads();
    }

#pragma unroll
    for (int i = 0; i < 8; i++) {
        int q = rowBase + ty * 8 + i;
        float* dst = &g_ctx[((size_t)(b * cS + q) * cH + h) * cDK + tx * 4];
        *(float4*)dst = *(float4*)&acc[i][0];
    }
}

// ---------------------------------------------------------------------------
// Kernel 5: output projection.  C = ctx @ Wout^T.  128x128x16 tile.
// ---------------------------------------------------------------------------
__global__ __launch_bounds__(256)
void outproj_kernel(const float* __restrict__ w_out,
                    float* __restrict__ out)
{
    __shared__ float As[16 * 132];
    __shared__ float Bs[16 * 132];

    const int tid = threadIdx.x;
    const int tx  = tid & 15;
    const int ty  = tid >> 4;
    const int rowBase = blockIdx.y * 128;
    const int colBase = blockIdx.x * 128;

    float acc[8][8] = {};

    for (int k0 = 0; k0 < cD; k0 += 16) {
#pragma unroll
        for (int t = 0; t < 2; t++) {
            int idx = tid + t * 256;
            int r   = idx >> 2;
            int c4  = (idx & 3) * 4;
            float4 a = *(const float4*)&g_ctx[(size_t)(rowBase + r) * cD + k0 + c4];
            As[(c4 + 0) * 132 + r] = a.x;
            As[(c4 + 1) * 132 + r] = a.y;
            As[(c4 + 2) * 132 + r] = a.z;
            As[(c4 + 3) * 132 + r] = a.w;
            float4 b = *(const float4*)&w_out[(size_t)(colBase + r) * cD + k0 + c4];
            Bs[(c4 + 0) * 132 + r] = b.x;
            Bs[(c4 + 1) * 132 + r] = b.y;
            Bs[(c4 + 2) * 132 + r] = b.z;
            Bs[(c4 + 3) * 132 + r] = b.w;
        }
        __syncthreads();
#pragma unroll
        for (int kk = 0; kk < 16; kk++) {
            float a[8], b[8];
            *(float4*)&a[0] = *(float4*)&As[kk * 132 + ty * 8];
            *(float4*)&a[4] = *(float4*)&As[kk * 132 + ty * 8 + 4];
            *(float4*)&b[0] = *(float4*)&Bs[kk * 132 + tx * 8];
            *(float4*)&b[4] = *(float4*)&Bs[kk * 132 + tx * 8 + 4];
#pragma unroll
            for (int i = 0; i < 8; i++)
#pragma unroll
                for (int j = 0; j < 8; j++)
                    acc[i][j] += a[i] * b[j];
        }
        __syncthreads();
    }

#pragma unroll
    for (int i = 0; i < 8; i++) {
        int m = rowBase + ty * 8 + i;
        float* dst = &out[(size_t)m * cD + colBase + tx * 8];
        *(float4*)&dst[0] = *(float4*)&acc[i][0];
        *(float4*)&dst[4] = *(float4*)&acc[i][4];
    }
}

// ---------------------------------------------------------------------------
// Launch
// ---------------------------------------------------------------------------
extern "C" void kernel_launch(void* const* d_in, const int* in_sizes, int n_in,
                              void* d_out, int out_size)
{
    const float* q_in  = (const float*)d_in[0];
    const float* k_in  = (const float*)d_in[1];
    const float* v_in  = (const float*)d_in[2];
    const float* w_in  = (const float*)d_in[3];
    const float* w_out = (const float*)d_in[4];

    float* out = (float*)d_out;                       // attn: B*S*D
    float* sim = out + (size_t)cB * cS * cD;          // sim_mean: B*S*S

    proj_kernel<<<dim3(cD / 128, (cB * cS) / 128, 3), 256>>>(q_in, k_in, v_in, w_in);
    scores_kernel<<<dim3(cS / 128, cS / 128, cBH), 256>>>();
    softmax_simmean_kernel<<<dim3(cS, cB), 256>>>(sim);
    pv_kernel<<<dim3(cS / 128, cBH), 256>>>();
    outproj_kernel<<<dim3(cD / 128, (cB * cS) / 128), 256>>>(w_out, out);
}

// round 9
// speedup vs baseline: 2.9348x; 1.4532x over previous
#include <cuda_runtime.h>
#include <cuda_bf16.h>
#include <stdint.h>
#include <math.h>

// Problem constants
constexpr int cB  = 4;
constexpr int cS  = 2048;
constexpr int cD  = 1024;
constexpr int cH  = 16;
constexpr int cDK = 64;
constexpr int cBH = cB * cH;   // 64

// Scratch
__device__ float g_q[(size_t)cBH * cS * cDK];   // (B,H,S,DK), q pre-scaled 0.125
__device__ float g_k[(size_t)cBH * cS * cDK];   // (B,H,S,DK)
__device__ float g_v[(size_t)cBH * cDK * cS];   // (B,H,DK,S)  V TRANSPOSED
__device__ float g_p[(size_t)cBH * cS * cS];    // (B,H,S,S)
__device__ float g_ctx[(size_t)cB * cS * cD];   // (B,S,H,DK)

// ---------------------------------------------------------------------------
// helpers
// ---------------------------------------------------------------------------
__device__ __forceinline__ uint32_t smem_u32(const void* p) {
    uint32_t a;
    asm("{ .reg .u64 t; cvta.to.shared.u64 t, %1; cvt.u32.u64 %0, t; }" : "=r"(a) : "l"(p));
    return a;
}

__device__ __forceinline__ void ldsm4(uint32_t (&r)[4], uint32_t addr) {
    asm volatile("ldmatrix.sync.aligned.m8n8.x4.shared.b16 {%0,%1,%2,%3}, [%4];"
        : "=r"(r[0]), "=r"(r[1]), "=r"(r[2]), "=r"(r[3]) : "r"(addr));
}

__device__ __forceinline__ void mma16816(float (&d)[4], const uint32_t (&a)[4],
                                         uint32_t b0, uint32_t b1) {
    asm volatile("mma.sync.aligned.m16n8k16.row.col.f32.bf16.bf16.f32 "
        "{%0,%1,%2,%3},{%4,%5,%6,%7},{%8,%9},{%0,%1,%2,%3};"
        : "+f"(d[0]), "+f"(d[1]), "+f"(d[2]), "+f"(d[3])
        : "r"(a[0]), "r"(a[1]), "r"(a[2]), "r"(a[3]), "r"(b0), "r"(b1));
}

// fp32 -> hi/lo bf16 split
__device__ __forceinline__ void bf16split(float x, uint16_t& h, uint16_t& l) {
    __nv_bfloat16 bh = __float2bfloat16_rn(x);
    float r = x - __bfloat162float(bh);
    __nv_bfloat16 bl = __float2bfloat16_rn(r);
    h = __bfloat16_as_ushort(bh);
    l = __bfloat16_as_ushort(bl);
}

// ---------------------------------------------------------------------------
// Generic NT GEMM via mma.sync bf16x3:  D[m,n] = sum_k A[m,k]*B[n,k]
// BM=128, BN in {128,64}, BK=32, 256 threads (8 warps).
// MODE 0: C[m*ldc+n] = v*scale
// MODE 1: proj scatter   C[((bb*16+h)*2048+ss)*64+dd] = v*scale
// MODE 2: proj scatterT  C[((bb*16+h)*64+dd)*2048+ss] = v*scale   (V transpose)
// MODE 3: pv scatter     C[((bb*2048+m)*16+h)*64+n]   = v*scale   (bh=blockIdx.z)
// ---------------------------------------------------------------------------
template<int BN, int MODE>
__global__ __launch_bounds__(256)
void gemm_mma(const float* __restrict__ A, long long aStrZ, int lda,
              const float* __restrict__ B, long long bStrZ, int ldb,
              float* __restrict__ C, long long cStrZ, int ldc,
              int Ktot, float scale)
{
    constexpr int BM = 128, BK = 32;
    constexpr int WARPS_N = BN / 32;        // 4 or 2
    constexpr int WARPS_M = 8 / WARPS_N;    // 2 or 4
    constexpr int WM = BM / WARPS_M;        // 64 or 32
    constexpr int MT = WM / 16;             // 4 or 2
    constexpr int ROWB = 80;                // smem row stride bytes (32 bf16 + pad)
    constexpr int A4 = BM * BK / (4 * 256); // 4 float4/thread
    constexpr int B4 = BN * BK / (4 * 256); // 4 or 2

    __shared__ __align__(16) uint8_t sAhi[BM * ROWB];
    __shared__ __align__(16) uint8_t sAlo[BM * ROWB];
    __shared__ __align__(16) uint8_t sBhi[BN * ROWB];
    __shared__ __align__(16) uint8_t sBlo[BN * ROWB];

    const int tid  = threadIdx.x;
    const int lane = tid & 31;
    const int wid  = tid >> 5;
    const int warpM = wid / WARPS_N;
    const int warpN = wid % WARPS_N;
    const int mBase = blockIdx.y * BM;
    const int nBase = blockIdx.x * BN;

    const float* a = A + (size_t)blockIdx.z * aStrZ;
    const float* b = B + (size_t)blockIdx.z * bStrZ;
    float*       c = C + (size_t)blockIdx.z * cStrZ;

    float4 aR[A4], bR[B4];

    float acc[MT][4][4];
#pragma unroll
    for (int mt = 0; mt < MT; mt++)
#pragma unroll
        for (int nt = 0; nt < 4; nt++)
#pragma unroll
            for (int i = 0; i < 4; i++) acc[mt][nt][i] = 0.0f;

    const int nIter = Ktot / BK;

    // --- prefetch chunk 0 ---
    {
        const int k0 = 0;
#pragma unroll
        for (int i = 0; i < A4; i++) {
            int idx = tid + i * 256, r = idx >> 3, c4 = (idx & 7) * 4;
            aR[i] = *(const float4*)(a + (size_t)(mBase + r) * lda + k0 + c4);
        }
#pragma unroll
        for (int i = 0; i < B4; i++) {
            int idx = tid + i * 256, r = idx >> 3, c4 = (idx & 7) * 4;
            bR[i] = *(const float4*)(b + (size_t)(nBase + r) * ldb + k0 + c4);
        }
    }

    // split+store helper (as macro-ish lambda)
    auto put = [&](uint8_t* hiB, uint8_t* loB, int r, int c4, float4 v) {
        uint16_t h0, l0, h1, l1, h2, l2, h3, l3;
        bf16split(v.x, h0, l0); bf16split(v.y, h1, l1);
        bf16split(v.z, h2, l2); bf16split(v.w, h3, l3);
        uint2 hu = make_uint2((uint32_t)h0 | ((uint32_t)h1 << 16),
                              (uint32_t)h2 | ((uint32_t)h3 << 16));
        uint2 lu = make_uint2((uint32_t)l0 | ((uint32_t)l1 << 16),
                              (uint32_t)l2 | ((uint32_t)l3 << 16));
        *(uint2*)(hiB + r * ROWB + c4 * 2) = hu;
        *(uint2*)(loB + r * ROWB + c4 * 2) = lu;
    };
    auto storeSmem = [&]() {
#pragma unroll
        for (int i = 0; i < A4; i++) {
            int idx = tid + i * 256, r = idx >> 3, c4 = (idx & 7) * 4;
            put(sAhi, sAlo, r, c4, aR[i]);
        }
#pragma unroll
        for (int i = 0; i < B4; i++) {
            int idx = tid + i * 256, r = idx >> 3, c4 = (idx & 7) * 4;
            put(sBhi, sBlo, r, c4, bR[i]);
        }
    };

    storeSmem();
    __syncthreads();

    // per-thread ldmatrix base addresses
    const uint32_t kHalfOff = (lane & 16) ? 16u : 0u;
    const uint32_t aHiBase = smem_u32(sAhi) + (warpM * WM + (lane & 15)) * ROWB + kHalfOff;
    const uint32_t aLoBase = smem_u32(sAlo) + (warpM * WM + (lane & 15)) * ROWB + kHalfOff;
    const uint32_t bHiBase = smem_u32(sBhi) + (warpN * 32 + (lane & 15)) * ROWB + kHalfOff;
    const uint32_t bLoBase = smem_u32(sBlo) + (warpN * 32 + (lane & 15)) * ROWB + kHalfOff;

    for (int it = 0; it < nIter; ++it) {
        // prefetch next chunk (LDG in flight during compute)
        if (it + 1 < nIter) {
            const int k0 = (it + 1) * BK;
#pragma unroll
            for (int i = 0; i < A4; i++) {
                int idx = tid + i * 256, r = idx >> 3, c4 = (idx & 7) * 4;
                aR[i] = *(const float4*)(a + (size_t)(mBase + r) * lda + k0 + c4);
            }
#pragma unroll
            for (int i = 0; i < B4; i++) {
                int idx = tid + i * 256, r = idx >> 3, c4 = (idx & 7) * 4;
                bR[i] = *(const float4*)(b + (size_t)(nBase + r) * ldb + k0 + c4);
            }
        }

        // ---- compute on current smem tiles ----
        {
            uint32_t ahi[MT][2][4], alo[MT][2][4];
            uint32_t bhi[2][2][4],  blo[2][2][4];   // [nt2][ks][4]
#pragma unroll
            for (int mt = 0; mt < MT; mt++)
#pragma unroll
                for (int ks = 0; ks < 2; ks++) {
                    ldsm4(ahi[mt][ks], aHiBase + mt * 16 * ROWB + ks * 32);
                    ldsm4(alo[mt][ks], aLoBase + mt * 16 * ROWB + ks * 32);
                }
#pragma unroll
            for (int nt2 = 0; nt2 < 2; nt2++)
#pragma unroll
                for (int ks = 0; ks < 2; ks++) {
                    ldsm4(bhi[nt2][ks], bHiBase + nt2 * 16 * ROWB + ks * 32);
                    ldsm4(blo[nt2][ks], bLoBase + nt2 * 16 * ROWB + ks * 32);
                }
#pragma unroll
            for (int ks = 0; ks < 2; ks++)
#pragma unroll
                for (int mt = 0; mt < MT; mt++)
#pragma unroll
                    for (int nt = 0; nt < 4; nt++) {
                        const int nt2 = nt >> 1, s = nt & 1;
                        mma16816(acc[mt][nt], ahi[mt][ks], bhi[nt2][ks][0 + s], bhi[nt2][ks][2 + s]);
                        mma16816(acc[mt][nt], ahi[mt][ks], blo[nt2][ks][0 + s], blo[nt2][ks][2 + s]);
                        mma16816(acc[mt][nt], alo[mt][ks], bhi[nt2][ks][0 + s], bhi[nt2][ks][2 + s]);
                    }
        }
        __syncthreads();
        if (it + 1 < nIter) {
            storeSmem();
            __syncthreads();
        }
    }

    // ---- epilogue: direct fragment stores ----
    const int lr  = lane >> 2;
    const int lc2 = (lane & 3) * 2;
#pragma unroll
    for (int mt = 0; mt < MT; mt++) {
#pragma unroll
        for (int nt = 0; nt < 4; nt++) {
            const int n0 = nBase + warpN * 32 + nt * 8 + lc2;
#pragma unroll
            for (int half = 0; half < 2; half++) {
                const int m = mBase + warpM * WM + mt * 16 + lr + half * 8;
                const float v0 = acc[mt][nt][half * 2 + 0] * scale;
                const float v1 = acc[mt][nt][half * 2 + 1] * scale;
                if (MODE == 0) {
                    *(float2*)&c[(size_t)m * ldc + n0] = make_float2(v0, v1);
                } else if (MODE == 1) {
                    const int bb = m >> 11, ss = m & 2047, h = n0 >> 6, dd = n0 & 63;
                    *(float2*)&c[(((size_t)(bb * 16 + h)) * 2048 + ss) * 64 + dd] = make_float2(v0, v1);
                } else if (MODE == 2) {
                    const int bb = m >> 11, ss = m & 2047, h = n0 >> 6, dd = n0 & 63;
                    c[(((size_t)(bb * 16 + h)) * 64 + dd)     * 2048 + ss] = v0;
                    c[(((size_t)(bb * 16 + h)) * 64 + dd + 1) * 2048 + ss] = v1;
                } else { // MODE 3
                    const int bh = blockIdx.z, bb = bh >> 4, h = bh & 15;
                    *(float2*)&c[(((size_t)(bb * 2048 + m)) * 16 + h) * 64 + n0] = make_float2(v0, v1);
                }
            }
        }
    }
}

// ---------------------------------------------------------------------------
// Fused softmax (in place) + head-mean.  One block per (b,q).  grid (S, B).
// ---------------------------------------------------------------------------
__global__ __launch_bounds__(256)
void softmax_simmean_kernel(float* __restrict__ sim)
{
    const int q = blockIdx.x;
    const int b = blockIdx.y;
    const int tid  = threadIdx.x;
    const int lane = tid & 31;
    const int wid  = tid >> 5;

    __shared__ float wred[8];
    float acc[8] = {};

    for (int h = 0; h < cH; h++) {
        float* p = g_p + ((size_t)(b * cH + h) * cS + q) * cS;

        float v[8];
        *(float4*)&v[0] = *(float4*)&p[tid * 8];
        *(float4*)&v[4] = *(float4*)&p[tid * 8 + 4];

        float m = v[0];
#pragma unroll
        for (int i = 1; i < 8; i++) m = fmaxf(m, v[i]);
#pragma unroll
        for (int o = 16; o > 0; o >>= 1) m = fmaxf(m, __shfl_xor_sync(0xffffffffu, m, o));
        if (lane == 0) wred[wid] = m;
        __syncthreads();
        float bm = wred[0];
#pragma unroll
        for (int w = 1; w < 8; w++) bm = fmaxf(bm, wred[w]);
        __syncthreads();

        float l = 0.0f;
#pragma unroll
        for (int i = 0; i < 8; i++) { v[i] = __expf(v[i] - bm); l += v[i]; }
#pragma unroll
        for (int o = 16; o > 0; o >>= 1) l += __shfl_xor_sync(0xffffffffu, l, o);
        if (lane == 0) wred[wid] = l;
        __syncthreads();
        float bl = wred[0];
#pragma unroll
        for (int w = 1; w < 8; w++) bl += wred[w];
        __syncthreads();

        const float inv = 1.0f / bl;
#pragma unroll
        for (int i = 0; i < 8; i++) { v[i] *= inv; acc[i] += v[i]; }
        *(float4*)&p[tid * 8]     = *(float4*)&v[0];
        *(float4*)&p[tid * 8 + 4] = *(float4*)&v[4];
    }

    float* s = sim + ((size_t)b * cS + q) * cS;
    float o0[8];
#pragma unroll
    for (int i = 0; i < 8; i++) o0[i] = acc[i] * (1.0f / cH);
    *(float4*)&s[tid * 8]     = *(float4*)&o0[0];
    *(float4*)&s[tid * 8 + 4] = *(float4*)&o0[4];
}

// ---------------------------------------------------------------------------
// Launch
// ---------------------------------------------------------------------------
extern "C" void kernel_launch(void* const* d_in, const int* in_sizes, int n_in,
                              void* d_out, int out_size)
{
    const float* q_in  = (const float*)d_in[0];
    const float* k_in  = (const float*)d_in[1];
    const float* v_in  = (const float*)d_in[2];
    const float* w_in  = (const float*)d_in[3];
    const float* w_out = (const float*)d_in[4];

    float* out = (float*)d_out;                    // attn: B*S*D
    float* sim = out + (size_t)cB * cS * cD;       // sim_mean: B*S*S

    void *pq, *pk, *pv, *pp, *pctx;
    cudaGetSymbolAddress(&pq, g_q);
    cudaGetSymbolAddress(&pk, g_k);
    cudaGetSymbolAddress(&pv, g_v);
    cudaGetSymbolAddress(&pp, g_p);
    cudaGetSymbolAddress(&pctx, g_ctx);

    // 1. Projections: M=8192, N=1024, K=1024 (NT vs W rows)
    dim3 gProj(cD / 128, (cB * cS) / 128, 1);
    gemm_mma<128, 1><<<gProj, 256>>>(q_in, 0, cD, w_in,                      0, cD,
                                     (float*)pq, 0, 0, cD, 0.125f);
    gemm_mma<128, 1><<<gProj, 256>>>(k_in, 0, cD, w_in + (size_t)cD * cD,    0, cD,
                                     (float*)pk, 0, 0, cD, 1.0f);
    gemm_mma<128, 2><<<gProj, 256>>>(v_in, 0, cD, w_in + (size_t)2 * cD * cD, 0, cD,
                                     (float*)pv, 0, 0, cD, 1.0f);

    // 2. Scores: per (b,h) M=N=2048, K=64 -> g_p
    dim3 gSc(cS / 128, cS / 128, cBH);
    gemm_mma<128, 0><<<gSc, 256>>>((const float*)pq, (long long)cS * cDK, cDK,
                                   (const float*)pk, (long long)cS * cDK, cDK,
                                   (float*)pp, (long long)cS * cS, cS, cDK, 1.0f);

    // 3. Softmax + head mean
    softmax_simmean_kernel<<<dim3(cS, cB), 256>>>(sim);

    // 4. PV: per (b,h) M=2048, N=64 (dk), K=2048, B = V^T rows -> g_ctx (B,S,H,DK)
    dim3 gPV(1, cS / 128, cBH);
    gemm_mma<64, 3><<<gPV, 256>>>((const float*)pp, (long long)cS * cS, cS,
                                  (const float*)pv, (long long)cDK * cS, cS,
                                  (float*)pctx, 0, 0, cS, 1.0f);

    // 5. Output projection: M=8192, N=1024, K=1024 -> out
    dim3 gOut(cD / 128, (cB * cS) / 128, 1);
    gemm_mma<128, 0><<<gOut, 256>>>((const float*)pctx, 0, cD, w_out, 0, cD,
                                    out, 0, cD, cD, 1.0f);
}

// round 10
// speedup vs baseline: 3.7449x; 1.2760x over previous
#include <cuda_runtime.h>
#include <cuda_bf16.h>
#include <stdint.h>
#include <math.h>

// Problem constants
constexpr int cB  = 4;
constexpr int cS  = 2048;
constexpr int cD  = 1024;
constexpr int cH  = 16;
constexpr int cDK = 64;
constexpr int cBH = cB * cH;   // 64

constexpr size_t N_X   = (size_t)3 * cB * cS * cD;      // 25.2M
constexpr size_t N_W   = (size_t)4 * cD * cD;           // 4M (w_in x3 + w_out)
constexpr size_t N_QK  = (size_t)cBH * cS * cDK;        // 8.4M
constexpr size_t N_P   = (size_t)cBH * cS * cS;         // 268M
constexpr size_t N_CTX = (size_t)cB * cS * cD;          // 8.4M

// bf16 hi/lo planes
__device__ __nv_bfloat16 g_xhi[N_X],  g_xlo[N_X];
__device__ __nv_bfloat16 g_whi[N_W],  g_wlo[N_W];
__device__ __nv_bfloat16 g_qhi[N_QK], g_qlo[N_QK];      // (B,H,S,DK) q pre-scaled
__device__ __nv_bfloat16 g_khi[N_QK], g_klo[N_QK];      // (B,H,S,DK)
__device__ __nv_bfloat16 g_vhi[N_QK], g_vlo[N_QK];      // (B,H,DK,S) transposed
__device__ float         g_p[N_P];                      // fp32 scores
__device__ __nv_bfloat16 g_phi[N_P],  g_plo[N_P];       // prob planes
__device__ __nv_bfloat16 g_chi[N_CTX], g_clo[N_CTX];    // ctx planes (B,S,H*DK)

// ---------------------------------------------------------------------------
// helpers
// ---------------------------------------------------------------------------
__device__ __forceinline__ uint32_t smem_u32(const void* p) {
    uint32_t a;
    asm("{ .reg .u64 t; cvta.to.shared.u64 t, %1; cvt.u32.u64 %0, t; }" : "=r"(a) : "l"(p));
    return a;
}
__device__ __forceinline__ void cpa16(uint32_t dst, const void* src) {
    asm volatile("cp.async.cg.shared.global [%0], [%1], 16;" :: "r"(dst), "l"(src));
}
__device__ __forceinline__ void ldsm4(uint32_t (&r)[4], uint32_t addr) {
    asm volatile("ldmatrix.sync.aligned.m8n8.x4.shared.b16 {%0,%1,%2,%3}, [%4];"
        : "=r"(r[0]), "=r"(r[1]), "=r"(r[2]), "=r"(r[3]) : "r"(addr));
}
__device__ __forceinline__ void mma16816(float (&d)[4], const uint32_t (&a)[4],
                                         uint32_t b0, uint32_t b1) {
    asm volatile("mma.sync.aligned.m16n8k16.row.col.f32.bf16.bf16.f32 "
        "{%0,%1,%2,%3},{%4,%5,%6,%7},{%8,%9},{%0,%1,%2,%3};"
        : "+f"(d[0]), "+f"(d[1]), "+f"(d[2]), "+f"(d[3])
        : "r"(a[0]), "r"(a[1]), "r"(a[2]), "r"(a[3]), "r"(b0), "r"(b1));
}
__device__ __forceinline__ void bf16split(float x, __nv_bfloat16& h, __nv_bfloat16& l) {
    h = __float2bfloat16_rn(x);
    l = __float2bfloat16_rn(x - __bfloat162float(h));
}

// ---------------------------------------------------------------------------
// Elementwise fp32 -> (hi, lo) bf16 planes.  n4 = n/4.
// ---------------------------------------------------------------------------
__global__ __launch_bounds__(256)
void split_kernel(const float* __restrict__ src,
                  __nv_bfloat16* __restrict__ hi, __nv_bfloat16* __restrict__ lo,
                  int n4)
{
    int i = blockIdx.x * 256 + threadIdx.x;
    if (i >= n4) return;
    float4 x = ((const float4*)src)[i];
    __nv_bfloat16 h[4], l[4];
    bf16split(x.x, h[0], l[0]); bf16split(x.y, h[1], l[1]);
    bf16split(x.z, h[2], l[2]); bf16split(x.w, h[3], l[3]);
    ((uint2*)hi)[i] = *(uint2*)h;
    ((uint2*)lo)[i] = *(uint2*)l;
}

// ---------------------------------------------------------------------------
// NT GEMM, bf16x3 via mma.sync, cp.async 2-stage pipeline.
// D[m,n] = sum_k (Ahi+Alo)[m,k]*(Bhi+Blo)[n,k]  (drops lo*lo)
// BM=128, BN in {128,64}, BK=32, 256 threads.
// MODE 0: C[m*ldc+n] = v*scale                      (fp32)
// MODE 1: q/k planes  Chi/lo[((bb*16+h)*2048+ss)*64+dd] = split(v*scale)
// MODE 2: v planesT   Chi/lo[((bb*16+h)*64+dd)*2048+ss]
// MODE 3: ctx planes  Chi/lo[((bb*2048+m)*16+h)*64+n]    (bh = blockIdx.z)
// ---------------------------------------------------------------------------
template<int BN, int MODE>
__global__ __launch_bounds__(256)
void gemm_bf16x3(const __nv_bfloat16* __restrict__ Ahi, const __nv_bfloat16* __restrict__ Alo,
                 long long aStrZ, int lda,
                 const __nv_bfloat16* __restrict__ Bhi, const __nv_bfloat16* __restrict__ Blo,
                 long long bStrZ, int ldb,
                 float* __restrict__ C, __nv_bfloat16* __restrict__ Chi,
                 __nv_bfloat16* __restrict__ Clo,
                 long long cStrZ, int ldc, int Ktot, float scale)
{
    constexpr int BM = 128, BK = 32;
    constexpr int WARPS_N = BN / 32;          // 4 or 2
    constexpr int WARPS_M = 8 / WARPS_N;      // 2 or 4
    constexpr int WM = BM / WARPS_M;          // 64 or 32
    constexpr int MT = WM / 16;               // 4 or 2
    constexpr int ROWB = 80;                  // 32 bf16 (64B) + 16B pad
    constexpr uint32_t OFF_ALO = BM * ROWB;
    constexpr uint32_t OFF_BHI = 2u * BM * ROWB;
    constexpr uint32_t OFF_BLO = 2u * BM * ROWB + BN * ROWB;
    constexpr uint32_t STAGE   = (2u * BM + 2u * BN) * ROWB;

    extern __shared__ __align__(16) uint8_t smem[];
    const uint32_t smBase = smem_u32(smem);

    const int tid  = threadIdx.x;
    const int lane = tid & 31;
    const int wid  = tid >> 5;
    const int warpM = wid / WARPS_N;
    const int warpN = wid % WARPS_N;
    const int mBase = blockIdx.y * BM;
    const int nBase = blockIdx.x * BN;

    const __nv_bfloat16* ahi = Ahi + (size_t)blockIdx.z * aStrZ;
    const __nv_bfloat16* alo = Alo + (size_t)blockIdx.z * aStrZ;
    const __nv_bfloat16* bhi = Bhi + (size_t)blockIdx.z * bStrZ;
    const __nv_bfloat16* blo = Blo + (size_t)blockIdx.z * bStrZ;

    float acc[MT][4][4];
#pragma unroll
    for (int mt = 0; mt < MT; mt++)
#pragma unroll
        for (int nt = 0; nt < 4; nt++)
#pragma unroll
            for (int i = 0; i < 4; i++) acc[mt][nt][i] = 0.0f;

    const int nIter = Ktot / BK;

    auto issue = [&](int it, int s) {
        const int k0 = it * BK;
        const uint32_t sb = smBase + (uint32_t)s * STAGE;
#pragma unroll
        for (int i = 0; i < 2; i++) {                 // A: 128 rows x 4 chunks
            int idx = tid + i * 256;
            int r = idx >> 2, ce = (idx & 3) * 8;
            size_t g = (size_t)(mBase + r) * lda + k0 + ce;
            uint32_t d = sb + (uint32_t)(r * ROWB + ce * 2);
            cpa16(d, ahi + g);
            cpa16(d + OFF_ALO, alo + g);
        }
#pragma unroll
        for (int i = 0; i < BN / 64; i++) {           // B: BN rows x 4 chunks
            int idx = tid + i * 256;
            int r = idx >> 2, ce = (idx & 3) * 8;
            size_t g = (size_t)(nBase + r) * ldb + k0 + ce;
            uint32_t d = sb + OFF_BHI + (uint32_t)(r * ROWB + ce * 2);
            cpa16(d, bhi + g);
            cpa16(d + (OFF_BLO - OFF_BHI), blo + g);
        }
        asm volatile("cp.async.commit_group;" ::: "memory");
    };

    const uint32_t aoff = (uint32_t)((warpM * WM + (lane & 15)) * ROWB) + ((lane & 16) ? 16u : 0u);
    const uint32_t boff = (uint32_t)((warpN * 32 + (lane & 15)) * ROWB) + ((lane & 16) ? 16u : 0u);

    issue(0, 0);
    if (nIter > 1) issue(1, 1);

    for (int it = 0; it < nIter; ++it) {
        if (it + 1 < nIter) asm volatile("cp.async.wait_group 1;" ::: "memory");
        else                asm volatile("cp.async.wait_group 0;" ::: "memory");
        __syncthreads();

        const uint32_t sb = smBase + (uint32_t)(it & 1) * STAGE;
        const uint32_t aHiB = sb + aoff;
        const uint32_t aLoB = sb + OFF_ALO + aoff;
        const uint32_t bHiB = sb + OFF_BHI + boff;
        const uint32_t bLoB = sb + OFF_BLO + boff;

#pragma unroll
        for (int ks = 0; ks < 2; ks++) {
            uint32_t fahi[MT][4], falo[MT][4];
            uint32_t fbhi[2][4],  fblo[2][4];
#pragma unroll
            for (int mt = 0; mt < MT; mt++) {
                ldsm4(fahi[mt], aHiB + mt * 16 * ROWB + ks * 32);
                ldsm4(falo[mt], aLoB + mt * 16 * ROWB + ks * 32);
            }
#pragma unroll
            for (int nt2 = 0; nt2 < 2; nt2++) {
                ldsm4(fbhi[nt2], bHiB + nt2 * 16 * ROWB + ks * 32);
                ldsm4(fblo[nt2], bLoB + nt2 * 16 * ROWB + ks * 32);
            }
#pragma unroll
            for (int mt = 0; mt < MT; mt++)
#pragma unroll
                for (int nt = 0; nt < 4; nt++) {
                    const int nt2 = nt >> 1, s = nt & 1;
                    mma16816(acc[mt][nt], fahi[mt], fbhi[nt2][0 + s], fbhi[nt2][2 + s]);
                    mma16816(acc[mt][nt], fahi[mt], fblo[nt2][0 + s], fblo[nt2][2 + s]);
                    mma16816(acc[mt][nt], falo[mt], fbhi[nt2][0 + s], fbhi[nt2][2 + s]);
                }
        }
        __syncthreads();
        if (it + 2 < nIter) issue(it + 2, it & 1);
    }

    // ---- epilogue: direct fragment stores ----
    float*         c   = C   ? C   + (size_t)blockIdx.z * cStrZ : nullptr;
    __nv_bfloat16* chi = Chi ? Chi + (size_t)blockIdx.z * cStrZ : nullptr;
    __nv_bfloat16* clo = Clo ? Clo + (size_t)blockIdx.z * cStrZ : nullptr;

    const int lr  = lane >> 2;
    const int lc2 = (lane & 3) * 2;
#pragma unroll
    for (int mt = 0; mt < MT; mt++) {
#pragma unroll
        for (int nt = 0; nt < 4; nt++) {
            const int n0 = nBase + warpN * 32 + nt * 8 + lc2;
#pragma unroll
            for (int half = 0; half < 2; half++) {
                const int m = mBase + warpM * WM + mt * 16 + lr + half * 8;
                const float v0 = acc[mt][nt][half * 2 + 0] * scale;
                const float v1 = acc[mt][nt][half * 2 + 1] * scale;
                if (MODE == 0) {
                    *(float2*)&c[(size_t)m * ldc + n0] = make_float2(v0, v1);
                } else if (MODE == 1) {
                    const int bb = m >> 11, ss = m & 2047, h = n0 >> 6, dd = n0 & 63;
                    const size_t idx = (((size_t)(bb * 16 + h)) * 2048 + ss) * 64 + dd;
                    __nv_bfloat162 h2, l2;
                    bf16split(v0, h2.x, l2.x);
                    bf16split(v1, h2.y, l2.y);
                    *(__nv_bfloat162*)&chi[idx] = h2;
                    *(__nv_bfloat162*)&clo[idx] = l2;
                } else if (MODE == 2) {
                    const int bb = m >> 11, ss = m & 2047, h = n0 >> 6, dd = n0 & 63;
                    const size_t i0 = (((size_t)(bb * 16 + h)) * 64 + dd) * 2048 + ss;
                    const size_t i1 = (((size_t)(bb * 16 + h)) * 64 + dd + 1) * 2048 + ss;
                    __nv_bfloat16 h0, l0, h1, l1;
                    bf16split(v0, h0, l0);
                    bf16split(v1, h1, l1);
                    chi[i0] = h0; clo[i0] = l0;
                    chi[i1] = h1; clo[i1] = l1;
                } else { // MODE 3
                    const int bh = blockIdx.z, bb = bh >> 4, h = bh & 15;
                    const size_t idx = (((size_t)(bb * 2048 + m)) * 16 + h) * 64 + n0;
                    __nv_bfloat162 h2, l2;
                    bf16split(v0, h2.x, l2.x);
                    bf16split(v1, h2.y, l2.y);
                    *(__nv_bfloat162*)&chi[idx] = h2;
                    *(__nv_bfloat162*)&clo[idx] = l2;
                }
            }
        }
    }
}

// ---------------------------------------------------------------------------
// Fused softmax + head-mean.  Reads fp32 scores, writes bf16 hi/lo prob
// planes + fp32 sim.  One block per (b,q).  grid (S, B).
// ---------------------------------------------------------------------------
__global__ __launch_bounds__(256)
void softmax_simmean_kernel(float* __restrict__ sim)
{
    const int q = blockIdx.x;
    const int b = blockIdx.y;
    const int tid  = threadIdx.x;
    const int lane = tid & 31;
    const int wid  = tid >> 5;

    __shared__ float wred[8];
    float acc[8] = {};

    for (int h = 0; h < cH; h++) {
        const size_t rowOff = ((size_t)(b * cH + h) * cS + q) * cS;
        const float* p = g_p + rowOff;

        float v[8];
        *(float4*)&v[0] = *(float4*)&p[tid * 8];
        *(float4*)&v[4] = *(float4*)&p[tid * 8 + 4];

        float m = v[0];
#pragma unroll
        for (int i = 1; i < 8; i++) m = fmaxf(m, v[i]);
#pragma unroll
        for (int o = 16; o > 0; o >>= 1) m = fmaxf(m, __shfl_xor_sync(0xffffffffu, m, o));
        if (lane == 0) wred[wid] = m;
        __syncthreads();
        float bm = wred[0];
#pragma unroll
        for (int w = 1; w < 8; w++) bm = fmaxf(bm, wred[w]);
        __syncthreads();

        float l = 0.0f;
#pragma unroll
        for (int i = 0; i < 8; i++) { v[i] = __expf(v[i] - bm); l += v[i]; }
#pragma unroll
        for (int o = 16; o > 0; o >>= 1) l += __shfl_xor_sync(0xffffffffu, l, o);
        if (lane == 0) wred[wid] = l;
        __syncthreads();
        float bl = wred[0];
#pragma unroll
        for (int w = 1; w < 8; w++) bl += wred[w];
        __syncthreads();

        const float inv = 1.0f / bl;
        __nv_bfloat16 hi[8], lo[8];
#pragma unroll
        for (int i = 0; i < 8; i++) {
            v[i] *= inv;
            acc[i] += v[i];
            bf16split(v[i], hi[i], lo[i]);
        }
        *(uint4*)&g_phi[rowOff + tid * 8] = *(uint4*)hi;
        *(uint4*)&g_plo[rowOff + tid * 8] = *(uint4*)lo;
    }

    float* s = sim + ((size_t)b * cS + q) * cS;
    float o0[8];
#pragma unroll
    for (int i = 0; i < 8; i++) o0[i] = acc[i] * (1.0f / cH);
    *(float4*)&s[tid * 8]     = *(float4*)&o0[0];
    *(float4*)&s[tid * 8 + 4] = *(float4*)&o0[4];
}

// ---------------------------------------------------------------------------
// Launch
// ---------------------------------------------------------------------------
extern "C" void kernel_launch(void* const* d_in, const int* in_sizes, int n_in,
                              void* d_out, int out_size)
{
    const float* q_in  = (const float*)d_in[0];
    const float* k_in  = (const float*)d_in[1];
    const float* v_in  = (const float*)d_in[2];
    const float* w_in  = (const float*)d_in[3];
    const float* w_out = (const float*)d_in[4];

    float* out = (float*)d_out;
    float* sim = out + (size_t)cB * cS * cD;

    void *pxh, *pxl, *pwh, *pwl, *pqh, *pql, *pkh, *pkl, *pvh, *pvl;
    void *pp, *pph, *ppl, *pch, *pcl;
    cudaGetSymbolAddress(&pxh, g_xhi); cudaGetSymbolAddress(&pxl, g_xlo);
    cudaGetSymbolAddress(&pwh, g_whi); cudaGetSymbolAddress(&pwl, g_wlo);
    cudaGetSymbolAddress(&pqh, g_qhi); cudaGetSymbolAddress(&pql, g_qlo);
    cudaGetSymbolAddress(&pkh, g_khi); cudaGetSymbolAddress(&pkl, g_klo);
    cudaGetSymbolAddress(&pvh, g_vhi); cudaGetSymbolAddress(&pvl, g_vlo);
    cudaGetSymbolAddress(&pp,  g_p);
    cudaGetSymbolAddress(&pph, g_phi); cudaGetSymbolAddress(&ppl, g_plo);
    cudaGetSymbolAddress(&pch, g_chi); cudaGetSymbolAddress(&pcl, g_clo);

    __nv_bfloat16 *xh = (__nv_bfloat16*)pxh, *xl = (__nv_bfloat16*)pxl;
    __nv_bfloat16 *wh = (__nv_bfloat16*)pwh, *wl = (__nv_bfloat16*)pwl;

    const int SM128 = (2 * 128 + 2 * 128) * 80 * 2;   // 81920
    const int SM64  = (2 * 128 + 2 * 64) * 80 * 2;    // 61440
    cudaFuncSetAttribute((const void*)gemm_bf16x3<128, 0>, cudaFuncAttributeMaxDynamicSharedMemorySize, SM128);
    cudaFuncSetAttribute((const void*)gemm_bf16x3<128, 1>, cudaFuncAttributeMaxDynamicSharedMemorySize, SM128);
    cudaFuncSetAttribute((const void*)gemm_bf16x3<128, 2>, cudaFuncAttributeMaxDynamicSharedMemorySize, SM128);
    cudaFuncSetAttribute((const void*)gemm_bf16x3<64, 3>,  cudaFuncAttributeMaxDynamicSharedMemorySize, SM64);

    // 0. Split harness inputs into bf16 planes
    const size_t nX1 = (size_t)cB * cS * cD;          // 8.4M per input
    split_kernel<<<(int)(nX1 / 4 / 256), 256>>>(q_in, xh,            xl,            (int)(nX1 / 4));
    split_kernel<<<(int)(nX1 / 4 / 256), 256>>>(k_in, xh + nX1,      xl + nX1,      (int)(nX1 / 4));
    split_kernel<<<(int)(nX1 / 4 / 256), 256>>>(v_in, xh + 2 * nX1,  xl + 2 * nX1,  (int)(nX1 / 4));
    const size_t nW3 = (size_t)3 * cD * cD;
    split_kernel<<<(int)(nW3 / 4 / 256), 256>>>(w_in,  wh,        wl,        (int)(nW3 / 4));
    split_kernel<<<(int)(cD * cD / 4 / 256), 256>>>(w_out, wh + nW3, wl + nW3, (int)(cD * cD / 4));

    // 1. Projections: M=8192, N=1024, K=1024
    dim3 gProj(cD / 128, (cB * cS) / 128, 1);
    gemm_bf16x3<128, 1><<<gProj, 256, SM128>>>(
        xh, xl, 0, cD, wh, wl, 0, cD,
        nullptr, (__nv_bfloat16*)pqh, (__nv_bfloat16*)pql, 0, cD, cD, 0.125f);
    gemm_bf16x3<128, 1><<<gProj, 256, SM128>>>(
        xh + nX1, xl + nX1, 0, cD, wh + (size_t)cD * cD, wl + (size_t)cD * cD, 0, cD,
        nullptr, (__nv_bfloat16*)pkh, (__nv_bfloat16*)pkl, 0, cD, cD, 1.0f);
    gemm_bf16x3<128, 2><<<gProj, 256, SM128>>>(
        xh + 2 * nX1, xl + 2 * nX1, 0, cD, wh + (size_t)2 * cD * cD, wl + (size_t)2 * cD * cD, 0, cD,
        nullptr, (__nv_bfloat16*)pvh, (__nv_bfloat16*)pvl, 0, cD, cD, 1.0f);

    // 2. Scores: per (b,h) M=N=2048, K=64 -> g_p fp32
    dim3 gSc(cS / 128, cS / 128, cBH);
    gemm_bf16x3<128, 0><<<gSc, 256, SM128>>>(
        (const __nv_bfloat16*)pqh, (const __nv_bfloat16*)pql, (long long)cS * cDK, cDK,
        (const __nv_bfloat16*)pkh, (const __nv_bfloat16*)pkl, (long long)cS * cDK, cDK,
        (float*)pp, nullptr, nullptr, (long long)cS * cS, cS, cDK, 1.0f);

    // 3. Softmax + head mean -> prob planes + sim
    softmax_simmean_kernel<<<dim3(cS, cB), 256>>>(sim);

    // 4. PV: per (b,h) M=2048, N=64, K=2048 -> ctx planes
    dim3 gPV(1, cS / 128, cBH);
    gemm_bf16x3<64, 3><<<gPV, 256, SM64>>>(
        (const __nv_bfloat16*)pph, (const __nv_bfloat16*)ppl, (long long)cS * cS, cS,
        (const __nv_bfloat16*)pvh, (const __nv_bfloat16*)pvl, (long long)cDK * cS, cS,
        nullptr, (__nv_bfloat16*)pch, (__nv_bfloat16*)pcl, 0, cS, cS, 1.0f);

    // 5. Output projection: M=8192, N=1024, K=1024 -> out fp32
    dim3 gOut(cD / 128, (cB * cS) / 128, 1);
    gemm_bf16x3<128, 0><<<gOut, 256, SM128>>>(
        (const __nv_bfloat16*)pch, (const __nv_bfloat16*)pcl, 0, cD,
        wh + nW3, wl + nW3, 0, cD,
        out, nullptr, nullptr, 0, cD, cD, 1.0f);
}